// round 4
// baseline (speedup 1.0000x reference)
#include <cuda_runtime.h>
#include <cstdint>

#define HH 512
#define WW 512
#define BATCH 16
#define WORDS 16   // u32 words per row
#define SWD 8      // u64 words per row
#define TILE 64
#define ST 76      // smem row stride in floats

// Scratch: bit-packed strong/weak masks (uint64-aligned).
__device__ uint64_t g_strong[2 * BATCH * HH * SWD];   // 1 MB
__device__ uint64_t g_weak[2 * BATCH * HH * SWD];     // 1 MB
__device__ int g_cnt;
__device__ int g_done;

__device__ __forceinline__ int reflect_idx(int p, int n) {
    if (p < 0) p = -p;
    if (p >= n) p = 2 * n - 2 - p;
    return p;
}

// ---------------- Kernel 1: gray -> blur -> sobel+mag+bin (fused) -> NMS -> threshold ----------------
__global__ __launch_bounds__(288) void canny_state_kernel(
    const float* __restrict__ in0, const float* __restrict__ in1)
{
    __shared__ float A[72 * ST];            // gray, later mag
    __shared__ float Bsm[72 * ST];          // hblur
    __shared__ unsigned char bins[68 * 68];

    const int tx = blockIdx.x, ty = blockIdx.y, z = blockIdx.z;
    const int u = z >> 4, b = z & 15;
    const float* img = (u == 0 ? in0 : in1) + (size_t)b * 3 * HH * WW;
    const int TX = tx * TILE, TY = ty * TILE;
    const int tid = threadIdx.x;

    if (z == 0 && tx == 0 && ty == 0 && tid == 0) { g_cnt = 0; g_done = 0; }

    // Gaussian weights (sigma=1, 5 taps) — same formula as reference
    const float e2 = expf(-2.0f), e05 = expf(-0.5f);
    const float ssum = (((e2 + e05) + 1.0f) + e05) + e2;
    const float w0 = e2 / ssum, w1 = e05 / ssum, w2 = 1.0f / ssum;

    // ---- Phase 1: grayscale into A[72][ST] (global rows TY-4..TY+67, cols TX-4..TX+67)
    if (TX >= 4 && TX + 68 <= WW) {
        for (int t = tid; t < 72 * 18; t += 288) {
            int r = t / 18, c4 = t % 18;
            int rr = reflect_idx(TY - 4 + r, HH);
            const float* p = img + (size_t)rr * WW + (TX - 4) + 4 * c4;
            float4 rv = *(const float4*)p;
            float4 gv = *(const float4*)(p + HH * WW);
            float4 bv = *(const float4*)(p + 2 * HH * WW);
            float4 o;
            o.x = 0.299f * rv.x + 0.587f * gv.x + 0.114f * bv.x;
            o.y = 0.299f * rv.y + 0.587f * gv.y + 0.114f * bv.y;
            o.z = 0.299f * rv.z + 0.587f * gv.z + 0.114f * bv.z;
            o.w = 0.299f * rv.w + 0.587f * gv.w + 0.114f * bv.w;
            *(float4*)&A[r * ST + 4 * c4] = o;
        }
    } else {
        for (int t = tid; t < 72 * 72; t += 288) {
            int r = t / 72, c = t % 72;
            int rr = reflect_idx(TY - 4 + r, HH);
            int rc = reflect_idx(TX - 4 + c, WW);
            const float* p = img + (size_t)rr * WW + rc;
            A[r * ST + c] = 0.299f * p[0] + 0.587f * p[HH * WW] + 0.114f * p[2 * HH * WW];
        }
    }
    __syncthreads();

    // ---- Phase 2a: horizontal 5-tap blur. A(gray) -> Bsm(hblur), 72 rows x 68 cols
    for (int t = tid; t < 72 * 17; t += 288) {
        int r = t / 17, c4 = t % 17;
        float4 xa = *(const float4*)&A[r * ST + 4 * c4];
        float4 xb = *(const float4*)&A[r * ST + 4 * c4 + 4];
        float x0 = xa.x, x1 = xa.y, x2 = xa.z, x3 = xa.w;
        float x4 = xb.x, x5 = xb.y, x6 = xb.z, x7 = xb.w;
        float4 o;
        o.x = w0 * (x0 + x4) + w1 * (x1 + x3) + w2 * x2;
        o.y = w0 * (x1 + x5) + w1 * (x2 + x4) + w2 * x3;
        o.z = w0 * (x2 + x6) + w1 * (x3 + x5) + w2 * x4;
        o.w = w0 * (x3 + x7) + w1 * (x4 + x6) + w2 * x5;
        *(float4*)&Bsm[r * ST + 4 * c4] = o;
    }
    __syncthreads();

    // ---- Phase 2b+3 fused: vertical blur (register ring) + sobel + mag + bin.
    // Task = 4 mag rows x 4 cols. mag[r][c] <-> global (TY-1+r, TX-1+c). Bsm -> A(mag), bins.
    const float TAN22 = 0.41421356237309503f;  // tan(pi/8)
    for (int t = tid; t < 17 * 17; t += 288) {
        int rg = t / 17, c4 = t % 17;
        int r0 = 4 * rg;                  // mag rows r0..r0+3 (rows 66,67 are guarded garbage)
        float ring[5][8];
        float v[6][8];
        #pragma unroll
        for (int k = 0; k < 10; k++) {
            int rr = r0 + k; if (rr > 71) rr = 71;
            float4 xa = *(const float4*)&Bsm[rr * ST + 4 * c4];
            float4 xb = *(const float4*)&Bsm[rr * ST + 4 * c4 + 4];
            ring[k % 5][0] = xa.x; ring[k % 5][1] = xa.y; ring[k % 5][2] = xa.z; ring[k % 5][3] = xa.w;
            ring[k % 5][4] = xb.x; ring[k % 5][5] = xb.y; ring[k % 5][6] = xb.z; ring[k % 5][7] = xb.w;
            if (k >= 4) {
                int i = k - 4;
                #pragma unroll
                for (int c = 0; c < 8; c++)
                    v[i][c] = w0 * (ring[i % 5][c] + ring[(i + 4) % 5][c])
                            + w1 * (ring[(i + 1) % 5][c] + ring[(i + 3) % 5][c])
                            + w2 * ring[(i + 2) % 5][c];
            }
        }
        #pragma unroll
        for (int j = 0; j < 4; j++) {
            int r = r0 + j;
            float gxv[4], gyv[4];
            #pragma unroll
            for (int jj = 0; jj < 4; jj++) {
                float cd0 = v[j][jj + 2]     - v[j][jj];
                float cd1 = v[j + 1][jj + 2] - v[j + 1][jj];
                float cd2 = v[j + 2][jj + 2] - v[j + 2][jj];
                float cs0 = v[j][jj]     + 2.f * v[j][jj + 1]     + v[j][jj + 2];
                float cs2 = v[j + 2][jj] + 2.f * v[j + 2][jj + 1] + v[j + 2][jj + 2];
                gxv[jj] = cd0 + 2.f * cd1 + cd2;
                gyv[jj] = cs2 - cs0;
            }
            int gy_g = TY - 1 + r;
            bool row_ok = (gy_g >= 0) && (gy_g < HH) && (r < 66);
            float m4[4]; uchar4 bo;
            #pragma unroll
            for (int jj = 0; jj < 4; jj++) {
                int c = 4 * c4 + jj;
                int gx_g = TX - 1 + c;
                float mag = 0.f;
                if (row_ok && gx_g >= 0 && gx_g < WW)
                    mag = sqrtf(gxv[jj] * gxv[jj] + gyv[jj] * gyv[jj] + 1e-12f);
                m4[jj] = mag;
                float ax = fabsf(gxv[jj]), ay = fabsf(gyv[jj]);
                int bin;
                if (ay <= TAN22 * ax)      bin = 0;
                else if (ax <= TAN22 * ay) bin = 2;
                else bin = ((gxv[jj] > 0.f) == (gyv[jj] > 0.f)) ? 1 : 3;
                ((unsigned char*)&bo)[jj] = (unsigned char)bin;
            }
            *(float4*)&A[r * ST + 4 * c4] = make_float4(m4[0], m4[1], m4[2], m4[3]);
            *(uchar4*)&bins[r * 68 + 4 * c4] = bo;
        }
    }
    __syncthreads();

    // ---- Phase 4: NMS + double threshold, bit-pack via ballot (mag in A)
    const int wp = tid >> 5, l = tid & 31;
    uint32_t* gs32 = (uint32_t*)g_strong;
    uint32_t* gw32 = (uint32_t*)g_weak;
    for (int t = wp; t < 128; t += 9) {   // 64 rows x 2 column-segments, 9 warps
        int r = t >> 1, seg = t & 1;
        int c = seg * 32 + l;
        int mr = r + 1, mc = c + 1;
        int bin = bins[mr * 68 + mc];
        int dy = (bin == 0) ? 0 : 1;
        int dx = (bin == 2) ? 0 : ((bin == 3) ? -1 : 1);
        float magc = A[mr * ST + mc];
        float n1 = A[(mr + dy) * ST + (mc + dx)];
        float n2 = A[(mr - dy) * ST + (mc - dx)];
        bool keep = (magc >= n1) && (magc >= n2);
        float nms = keep ? magc : 0.f;
        bool strong = (nms >= 0.2f);
        bool weak = (!strong) && (nms >= 0.1f);
        unsigned sm = __ballot_sync(0xffffffffu, strong);
        unsigned wm = __ballot_sync(0xffffffffu, weak);
        if (l == 0) {
            size_t idx = (((size_t)(u * BATCH + b) * HH) + (TY + r)) * WORDS + (tx * 2 + seg);
            gs32[idx] = sm;
            gw32[idx] = wm;
        }
    }
}

// ---------------- Kernel 2: 10x hysteresis (uint64, full-width strips) + count + finalize ---------
#define SROWS 84    // 64 + 2*10 halo rows
#define SPITCH 10   // padded S row (1 u64 pad each side)

__global__ __launch_bounds__(448) void hyst_count_kernel(float* __restrict__ out)
{
    __shared__ uint64_t Ssh[2][SROWS][SPITCH];        // 13.4 KB
    __shared__ uint64_t Hsh[2][SROWS + 2][SWD];       // 11.0 KB
    __shared__ int warpsum[14];

    const int SY = blockIdx.x * 64;
    const int b = blockIdx.y;
    const int tid = threadIdx.x;

    // zero pads
    for (int i = tid; i < 2 * SROWS; i += 448) {
        int uu = i / SROWS, r = i % SROWS;
        Ssh[uu][r][0] = 0; Ssh[uu][r][SPITCH - 1] = 0;
    }
    if (tid < 2 * SWD) {
        int uu = tid / SWD, w = tid % SWD;
        Hsh[uu][0][w] = 0; Hsh[uu][SROWS + 1][w] = 0;
    }

    // 3 tasks per thread (1344 = 448*3), decomposed once
    int uu_[3], r_[3], w_[3];
    uint64_t s_[3], wk_[3], h_[3];
    uint64_t *pS[3], *pH[3];
    #pragma unroll
    for (int q = 0; q < 3; q++) {
        int t = tid + q * 448;
        int uu = t / 672, rem = t % 672;
        int r = rem >> 3, w = rem & 7;
        uu_[q] = uu; r_[q] = r; w_[q] = w;
        int gy = SY - 10 + r;
        uint64_t sv = 0, wv = 0;
        if (gy >= 0 && gy < HH) {
            size_t idx = (((size_t)(uu * BATCH + b)) * HH + gy) * SWD + w;
            sv = g_strong[idx];
            wv = g_weak[idx];
        }
        s_[q] = sv; wk_[q] = wv;
        pS[q] = &Ssh[uu][r][w + 1];
        pH[q] = &Hsh[uu][r + 1][w];
        *pS[q] = sv;
    }
    __syncthreads();

    for (int it = 0; it < 10; it++) {
        #pragma unroll
        for (int q = 0; q < 3; q++) {
            uint64_t s = s_[q];
            uint64_t lf = pS[q][-1], rt = pS[q][1];
            uint64_t h = s | (s << 1) | (s >> 1) | (lf >> 63) | (rt << 63);
            h_[q] = h;
            *pH[q] = h;
        }
        __syncthreads();
        #pragma unroll
        for (int q = 0; q < 3; q++) {
            uint64_t nb = h_[q] | pH[q][-SWD] | pH[q][SWD];
            uint64_t pr = wk_[q] & nb;
            s_[q] |= pr;
            wk_[q] &= ~pr;
            *pS[q] = s_[q];
        }
        __syncthreads();
    }

    // XOR-popcount over 64-row interior (r in 10..73)
    int cnt = 0;
    #pragma unroll
    for (int q = 0; q < 3; q++) {
        if (uu_[q] == 0 && r_[q] >= 10 && r_[q] < 74)
            cnt += __popcll(s_[q] ^ Ssh[1][r_[q]][w_[q] + 1]);
    }
    #pragma unroll
    for (int off = 16; off; off >>= 1)
        cnt += __shfl_down_sync(0xffffffffu, cnt, off);
    if ((tid & 31) == 0) warpsum[tid >> 5] = cnt;
    __syncthreads();
    if (tid == 0) {
        int tot = 0;
        #pragma unroll
        for (int k = 0; k < 14; k++) tot += warpsum[k];
        atomicAdd(&g_cnt, tot);
        __threadfence();
        int ticket = atomicAdd(&g_done, 1);
        if (ticket == 8 * BATCH - 1) {
            int total = atomicAdd(&g_cnt, 0);
            out[0] = (float)total / 4194304.0f;  // 16*512*512
        }
    }
}

extern "C" void kernel_launch(void* const* d_in, const int* in_sizes, int n_in,
                              void* d_out, int out_size) {
    const float* y_hat = (const float*)d_in[0];
    const float* y     = (const float*)d_in[1];
    float* out = (float*)d_out;

    dim3 g1(WW / TILE, HH / TILE, 2 * BATCH);   // 8 x 8 x 32
    canny_state_kernel<<<g1, 288>>>(y_hat, y);
    dim3 g2(HH / TILE, BATCH);                  // 8 x 16 strips
    hyst_count_kernel<<<g2, 448>>>(out);
}

// round 5
// speedup vs baseline: 1.1414x; 1.1414x over previous
#include <cuda_runtime.h>
#include <cstdint>

#define HH 512
#define WW 512
#define BATCH 16
#define WORDS 16   // u32 words per row
#define SWD 8      // u64 words per row
#define TILE 64
#define ST 76      // smem row stride in floats

// Scratch: bit-packed strong/weak masks (uint64-aligned).
__device__ uint64_t g_strong[2 * BATCH * HH * SWD];   // 1 MB
__device__ uint64_t g_weak[2 * BATCH * HH * SWD];     // 1 MB
__device__ int g_cnt;
__device__ int g_done;

__device__ __forceinline__ int reflect_idx(int p, int n) {
    if (p < 0) p = -p;
    if (p >= n) p = 2 * n - 2 - p;
    return p;
}

// ---------------- Kernel 1: gray -> blur -> sobel+mag+bin -> NMS -> threshold ----------------
#define NT 512
__global__ __launch_bounds__(NT) void canny_state_kernel(
    const float* __restrict__ in0, const float* __restrict__ in1)
{
    __shared__ float A[72 * ST];            // gray -> blur(Bm)
    __shared__ float Bsm[72 * ST];          // hblur -> mag
    __shared__ unsigned char bins[68 * 68];

    const int tx = blockIdx.x, ty = blockIdx.y, z = blockIdx.z;
    const int u = z >> 4, b = z & 15;
    const float* img = (u == 0 ? in0 : in1) + (size_t)b * 3 * HH * WW;
    const int TX = tx * TILE, TY = ty * TILE;
    const int tid = threadIdx.x;

    if (z == 0 && tx == 0 && ty == 0 && tid == 0) { g_cnt = 0; g_done = 0; }

    // Gaussian weights (sigma=1, 5 taps) — same formula as reference
    const float e2 = expf(-2.0f), e05 = expf(-0.5f);
    const float ssum = (((e2 + e05) + 1.0f) + e05) + e2;
    const float w0 = e2 / ssum, w1 = e05 / ssum, w2 = 1.0f / ssum;

    // ---- Phase 1: grayscale into A[72][ST] (global rows TY-4..TY+67, cols TX-4..TX+67)
    if (TX >= 4 && TX + 68 <= WW) {
        for (int t = tid; t < 72 * 18; t += NT) {
            int r = t / 18, c4 = t % 18;
            int rr = reflect_idx(TY - 4 + r, HH);
            const float* p = img + (size_t)rr * WW + (TX - 4) + 4 * c4;
            float4 rv = *(const float4*)p;
            float4 gv = *(const float4*)(p + HH * WW);
            float4 bv = *(const float4*)(p + 2 * HH * WW);
            float4 o;
            o.x = 0.299f * rv.x + 0.587f * gv.x + 0.114f * bv.x;
            o.y = 0.299f * rv.y + 0.587f * gv.y + 0.114f * bv.y;
            o.z = 0.299f * rv.z + 0.587f * gv.z + 0.114f * bv.z;
            o.w = 0.299f * rv.w + 0.587f * gv.w + 0.114f * bv.w;
            *(float4*)&A[r * ST + 4 * c4] = o;
        }
    } else {
        for (int t = tid; t < 72 * 72; t += NT) {
            int r = t / 72, c = t % 72;
            int rr = reflect_idx(TY - 4 + r, HH);
            int rc = reflect_idx(TX - 4 + c, WW);
            const float* p = img + (size_t)rr * WW + rc;
            A[r * ST + c] = 0.299f * p[0] + 0.587f * p[HH * WW] + 0.114f * p[2 * HH * WW];
        }
    }
    __syncthreads();

    // ---- Phase 2a: horizontal 5-tap blur. A(gray) -> Bsm(hblur), 72 rows x 68 cols
    for (int t = tid; t < 72 * 17; t += NT) {
        int r = t / 17, c4 = t % 17;
        float4 xa = *(const float4*)&A[r * ST + 4 * c4];
        float4 xb = *(const float4*)&A[r * ST + 4 * c4 + 4];
        float x0 = xa.x, x1 = xa.y, x2 = xa.z, x3 = xa.w;
        float x4 = xb.x, x5 = xb.y, x6 = xb.z, x7 = xb.w;
        float4 o;
        o.x = w0 * (x0 + x4) + w1 * (x1 + x3) + w2 * x2;
        o.y = w0 * (x1 + x5) + w1 * (x2 + x4) + w2 * x3;
        o.z = w0 * (x2 + x6) + w1 * (x3 + x5) + w2 * x4;
        o.w = w0 * (x3 + x7) + w1 * (x4 + x6) + w2 * x5;
        *(float4*)&Bsm[r * ST + 4 * c4] = o;
    }
    __syncthreads();

    // ---- Phase 2b: vertical 5-tap blur. Bsm(hblur) -> A(Bm), 68 rows x 68 cols, 4-row block
    for (int t = tid; t < 17 * 17; t += NT) {
        int rg = t / 17, c4 = t % 17;
        float4 y[8];
        #pragma unroll
        for (int k = 0; k < 8; k++) y[k] = *(const float4*)&Bsm[(4 * rg + k) * ST + 4 * c4];
        #pragma unroll
        for (int j = 0; j < 4; j++) {
            float4 o;
            o.x = w0 * (y[j].x + y[j + 4].x) + w1 * (y[j + 1].x + y[j + 3].x) + w2 * y[j + 2].x;
            o.y = w0 * (y[j].y + y[j + 4].y) + w1 * (y[j + 1].y + y[j + 3].y) + w2 * y[j + 2].y;
            o.z = w0 * (y[j].z + y[j + 4].z) + w1 * (y[j + 1].z + y[j + 3].z) + w2 * y[j + 2].z;
            o.w = w0 * (y[j].w + y[j + 4].w) + w1 * (y[j + 1].w + y[j + 3].w) + w2 * y[j + 2].w;
            *(float4*)&A[(4 * rg + j) * ST + 4 * c4] = o;
        }
    }
    __syncthreads();

    // ---- Phase 3: fused sobel + magnitude + direction bin. A(Bm) -> Bsm(mag), bins
    // mag[r][c] corresponds to global pixel (TY-1+r, TX-1+c), r,c in 0..65
    const float TAN22 = 0.41421356237309503f;  // tan(pi/8)
    for (int t = tid; t < 66 * 17; t += NT) {
        int r = t / 17, c4 = t % 17;
        float cs[3][4], cd[3][4];
        #pragma unroll
        for (int i = 0; i < 3; i++) {
            float4 xa = *(const float4*)&A[(r + i) * ST + 4 * c4];
            float4 xb = *(const float4*)&A[(r + i) * ST + 4 * c4 + 4];
            float x0 = xa.x, x1 = xa.y, x2 = xa.z, x3 = xa.w;
            float x4 = xb.x, x5 = xb.y, x6 = xb.z;
            cs[i][0] = x0 + 2.f * x1 + x2;  cd[i][0] = x2 - x0;
            cs[i][1] = x1 + 2.f * x2 + x3;  cd[i][1] = x3 - x1;
            cs[i][2] = x2 + 2.f * x3 + x4;  cd[i][2] = x4 - x2;
            cs[i][3] = x3 + 2.f * x4 + x5;  cd[i][3] = x5 - x3;
        }
        int gy_g = TY - 1 + r;
        bool row_ok = (gy_g >= 0) && (gy_g < HH);
        float m4[4]; uchar4 bo;
        #pragma unroll
        for (int jj = 0; jj < 4; jj++) {
            int c = 4 * c4 + jj;
            float gxv = cd[0][jj] + 2.f * cd[1][jj] + cd[2][jj];
            float gyv = cs[2][jj] - cs[0][jj];
            int gx_g = TX - 1 + c;
            float mag = 0.f;
            if (row_ok && gx_g >= 0 && gx_g < WW)
                mag = sqrtf(gxv * gxv + gyv * gyv + 1e-12f);
            m4[jj] = mag;
            float ax = fabsf(gxv), ay = fabsf(gyv);
            int bin;
            if (ay <= TAN22 * ax)      bin = 0;
            else if (ax <= TAN22 * ay) bin = 2;
            else bin = ((gxv > 0.f) == (gyv > 0.f)) ? 1 : 3;
            ((unsigned char*)&bo)[jj] = (unsigned char)bin;
        }
        *(float4*)&Bsm[r * ST + 4 * c4] = make_float4(m4[0], m4[1], m4[2], m4[3]);
        *(uchar4*)&bins[r * 68 + 4 * c4] = bo;
    }
    __syncthreads();

    // ---- Phase 4: NMS + double threshold, bit-pack via ballot (mag in Bsm)
    const int wp = tid >> 5, l = tid & 31;
    uint32_t* gs32 = (uint32_t*)g_strong;
    uint32_t* gw32 = (uint32_t*)g_weak;
    for (int t = wp; t < 128; t += NT / 32) {   // 64 rows x 2 column-segments
        int r = t >> 1, seg = t & 1;
        int c = seg * 32 + l;
        int mr = r + 1, mc = c + 1;
        int bin = bins[mr * 68 + mc];
        int dy = (bin == 0) ? 0 : 1;
        int dx = (bin == 2) ? 0 : ((bin == 3) ? -1 : 1);
        float magc = Bsm[mr * ST + mc];
        float n1 = Bsm[(mr + dy) * ST + (mc + dx)];
        float n2 = Bsm[(mr - dy) * ST + (mc - dx)];
        bool keep = (magc >= n1) && (magc >= n2);
        float nms = keep ? magc : 0.f;
        bool strong = (nms >= 0.2f);
        bool weak = (!strong) && (nms >= 0.1f);
        unsigned sm = __ballot_sync(0xffffffffu, strong);
        unsigned wm = __ballot_sync(0xffffffffu, weak);
        if (l == 0) {
            size_t idx = (((size_t)(u * BATCH + b) * HH) + (TY + r)) * WORDS + (tx * 2 + seg);
            gs32[idx] = sm;
            gw32[idx] = wm;
        }
    }
}

// ---------------- Kernel 2: 10x hysteresis (uint64, full-width strips) + count + finalize ---------
#define SROWS 84    // 64 + 2*10 halo rows
#define SPITCH 10   // padded S row (1 u64 pad each side)

__global__ __launch_bounds__(448) void hyst_count_kernel(float* __restrict__ out)
{
    __shared__ uint64_t Ssh[2][SROWS][SPITCH];        // 13.4 KB
    __shared__ uint64_t Hsh[2][SROWS + 2][SWD];       // 11.0 KB
    __shared__ int warpsum[14];

    const int SY = blockIdx.x * 64;
    const int b = blockIdx.y;
    const int tid = threadIdx.x;

    // zero pads
    for (int i = tid; i < 2 * SROWS; i += 448) {
        int uu = i / SROWS, r = i % SROWS;
        Ssh[uu][r][0] = 0; Ssh[uu][r][SPITCH - 1] = 0;
    }
    if (tid < 2 * SWD) {
        int uu = tid / SWD, w = tid % SWD;
        Hsh[uu][0][w] = 0; Hsh[uu][SROWS + 1][w] = 0;
    }

    // 3 tasks per thread (1344 = 448*3), decomposed once
    int uu_[3], r_[3], w_[3];
    uint64_t s_[3], wk_[3], h_[3];
    uint64_t *pS[3], *pH[3];
    #pragma unroll
    for (int q = 0; q < 3; q++) {
        int t = tid + q * 448;
        int uu = t / 672, rem = t % 672;
        int r = rem >> 3, w = rem & 7;
        uu_[q] = uu; r_[q] = r; w_[q] = w;
        int gy = SY - 10 + r;
        uint64_t sv = 0, wv = 0;
        if (gy >= 0 && gy < HH) {
            size_t idx = (((size_t)(uu * BATCH + b)) * HH + gy) * SWD + w;
            sv = g_strong[idx];
            wv = g_weak[idx];
        }
        s_[q] = sv; wk_[q] = wv;
        pS[q] = &Ssh[uu][r][w + 1];
        pH[q] = &Hsh[uu][r + 1][w];
        *pS[q] = sv;
    }
    __syncthreads();

    for (int it = 0; it < 10; it++) {
        #pragma unroll
        for (int q = 0; q < 3; q++) {
            uint64_t s = s_[q];
            uint64_t lf = pS[q][-1], rt = pS[q][1];
            uint64_t h = s | (s << 1) | (s >> 1) | (lf >> 63) | (rt << 63);
            h_[q] = h;
            *pH[q] = h;
        }
        __syncthreads();
        #pragma unroll
        for (int q = 0; q < 3; q++) {
            uint64_t nb = h_[q] | pH[q][-SWD] | pH[q][SWD];
            uint64_t pr = wk_[q] & nb;
            s_[q] |= pr;
            wk_[q] &= ~pr;
            *pS[q] = s_[q];
        }
        __syncthreads();
    }

    // XOR-popcount over 64-row interior (r in 10..73)
    int cnt = 0;
    #pragma unroll
    for (int q = 0; q < 3; q++) {
        if (uu_[q] == 0 && r_[q] >= 10 && r_[q] < 74)
            cnt += __popcll(s_[q] ^ Ssh[1][r_[q]][w_[q] + 1]);
    }
    #pragma unroll
    for (int off = 16; off; off >>= 1)
        cnt += __shfl_down_sync(0xffffffffu, cnt, off);
    if ((tid & 31) == 0) warpsum[tid >> 5] = cnt;
    __syncthreads();
    if (tid == 0) {
        int tot = 0;
        #pragma unroll
        for (int k = 0; k < 14; k++) tot += warpsum[k];
        atomicAdd(&g_cnt, tot);
        __threadfence();
        int ticket = atomicAdd(&g_done, 1);
        if (ticket == 8 * BATCH - 1) {
            int total = atomicAdd(&g_cnt, 0);
            out[0] = (float)total / 4194304.0f;  // 16*512*512
        }
    }
}

extern "C" void kernel_launch(void* const* d_in, const int* in_sizes, int n_in,
                              void* d_out, int out_size) {
    const float* y_hat = (const float*)d_in[0];
    const float* y     = (const float*)d_in[1];
    float* out = (float*)d_out;

    dim3 g1(WW / TILE, HH / TILE, 2 * BATCH);   // 8 x 8 x 32
    canny_state_kernel<<<g1, NT>>>(y_hat, y);
    dim3 g2(HH / TILE, BATCH);                  // 8 x 16 strips
    hyst_count_kernel<<<g2, 448>>>(out);
}